// round 3
// baseline (speedup 1.0000x reference)
#include <cuda_runtime.h>
#include <cstdint>
#include <math.h>

#define N_PRIORS 268800
#define MAXK 750
#define CAP 4096          // candidate capacity (score > CTHR), power of two for bitonic
#define M1 2048           // sorted prefix length for bitmask NMS
#define W1 (M1 / 64)      // 32 u64 words per mask row (1 per warp lane)
#define CTHR 0.99f
#define NSUPW ((N_PRIORS + 31) / 32)

// ---------------- static device scratch (no allocations allowed) ----------------
__device__ float4 g_boxes[N_PRIORS];                    // decoded boxes, pixel coords
__device__ float  g_area[N_PRIORS];                     // (+1 convention) areas
__device__ unsigned long long g_ckeys[CAP];             // candidate keys (unordered)
__device__ int    g_cnt;                                // candidate count (may exceed CAP)
__device__ int    g_ncand;                              // min(g_cnt, CAP)
__device__ int    g_overflow;
__device__ int    g_sorder[CAP];                        // sorted original indices (desc score, stable)
__device__ float4 g_sbox[M1];
__device__ float  g_sarea[M1];
__device__ unsigned long long g_mask[(size_t)M1 * W1];  // row i: bits j>i that i suppresses
__device__ int    g_kept_idx[MAXK];                     // original indices of kept boxes
__device__ int    g_state[2];                           // [0]=kept count, [1]=done flag
__device__ unsigned int g_supp[NSUPW];                  // fallback suppression bitmap

// ---------------- prior computation (mirrors numpy float64 -> float32) ----------------
__device__ __forceinline__ void get_prior(int i, float& px, float& py, float& ps) {
    int r, f, step; float msf;
    if (i < 204800)      { r = i;          f = 320; step = 8;  msf = (r & 1) ? 32.0f  : 16.0f;  }
    else if (i < 256000) { r = i - 204800; f = 160; step = 16; msf = (r & 1) ? 128.0f : 64.0f;  }
    else                 { r = i - 256000; f = 80;  step = 32; msf = (r & 1) ? 512.0f : 256.0f; }
    int c = r >> 1;
    int x = c % f;
    int y = c / f;
    px = (float)((((double)x + 0.5) * (double)step) / 2560.0);
    py = (float)((((double)y + 0.5) * (double)step) / 2560.0);
    ps = (float)((double)msf / 2560.0);
}

// IoU with +1 area convention; op order mirrors the reference exactly.
// (bi, ai) = KEPT box, (bj, aj) = candidate  (matches area[idx] + area - inter).
__device__ __forceinline__ bool iou_gt(const float4 bi, const float ai,
                                       const float4 bj, const float aj) {
    float xx1 = fmaxf(bi.x, bj.x);
    float yy1 = fmaxf(bi.y, bj.y);
    float xx2 = fminf(bi.z, bj.z);
    float yy2 = fminf(bi.w, bj.w);
    float iw = fmaxf(0.0f, __fadd_rn(__fsub_rn(xx2, xx1), 1.0f));
    float ih = fmaxf(0.0f, __fadd_rn(__fsub_rn(yy2, yy1), 1.0f));
    float inter = __fmul_rn(iw, ih);
    float uni = __fsub_rn(__fadd_rn(ai, aj), inter);
    float iou = inter / uni;        // IEEE divide (-prec-div default true)
    return iou > 0.4f;
}

// ---------------- init ----------------
__global__ void init_kernel() {
    if (threadIdx.x == 0) { g_cnt = 0; g_state[0] = 0; g_state[1] = 0; g_overflow = 0; }
}

// ---------------- decode all boxes + candidate selection ----------------
__global__ void decode_kernel(const float* __restrict__ loc,
                              const float* __restrict__ scores) {
    int i = blockIdx.x * blockDim.x + threadIdx.x;
    if (i >= N_PRIORS) return;

    float px, py, ps;
    get_prior(i, px, py, ps);

    float4 l = reinterpret_cast<const float4*>(loc)[i];

    // cxcy = prior[:2] + (loc*0.1) * prior[2:]
    float cx = __fadd_rn(px, __fmul_rn(__fmul_rn(l.x, 0.1f), ps));
    float cy = __fadd_rn(py, __fmul_rn(__fmul_rn(l.y, 0.1f), ps));
    // wh = prior[2:] * exp(loc*0.2)
    float w = __fmul_rn(ps, expf(__fmul_rn(l.z, 0.2f)));
    float h = __fmul_rn(ps, expf(__fmul_rn(l.w, 0.2f)));

    float x1 = __fmul_rn(__fsub_rn(cx, __fmul_rn(w, 0.5f)), 2560.0f);
    float y1 = __fmul_rn(__fsub_rn(cy, __fmul_rn(h, 0.5f)), 2560.0f);
    float x2 = __fmul_rn(__fadd_rn(cx, __fmul_rn(w, 0.5f)), 2560.0f);
    float y2 = __fmul_rn(__fadd_rn(cy, __fmul_rn(h, 0.5f)), 2560.0f);

    g_boxes[i] = make_float4(x1, y1, x2, y2);
    g_area[i] = __fmul_rn(__fadd_rn(__fsub_rn(x2, x1), 1.0f),
                          __fadd_rn(__fsub_rn(y2, y1), 1.0f));

    float sc = scores[i];
    if (sc > CTHR) {
        int p = atomicAdd(&g_cnt, 1);
        if (p < CAP) {
            // descending by score bits, ties -> ascending original index (stable argsort)
            g_ckeys[p] = ((unsigned long long)__float_as_uint(sc) << 32)
                       | (unsigned long long)(0xFFFFFFFFu - (unsigned)i);
        }
    }
}

// ---------------- single-block bitonic sort (descending) + gather ----------------
__global__ void __launch_bounds__(1024, 1) sort_kernel() {
    __shared__ unsigned long long sk[CAP];   // 32 KB
    int tid = threadIdx.x;
    int cnt = g_cnt;
    int n = cnt < CAP ? cnt : CAP;

    for (int t = tid; t < CAP; t += 1024)
        sk[t] = (t < n) ? g_ckeys[t] : 0ULL;
    __syncthreads();

    for (int k = 2; k <= CAP; k <<= 1) {
        for (int j = k >> 1; j > 0; j >>= 1) {
            for (int t = tid; t < CAP; t += 1024) {
                int ixj = t ^ j;
                if (ixj > t) {
                    unsigned long long a = sk[t], b = sk[ixj];
                    bool desc = ((t & k) == 0);
                    bool sw = desc ? (a < b) : (a > b);
                    if (sw) { sk[t] = b; sk[ixj] = a; }
                }
            }
            __syncthreads();
        }
    }

    for (int t = tid; t < n; t += 1024) {
        int idx = (int)(0xFFFFFFFFu - (unsigned)(sk[t] & 0xFFFFFFFFull));
        g_sorder[t] = idx;
        if (t < M1) {
            g_sbox[t] = g_boxes[idx];
            g_sarea[t] = g_area[idx];
        }
    }
    if (tid == 0) {
        g_ncand = n;
        g_overflow = (cnt > CAP) ? 1 : 0;
    }
}

// ---------------- triangular suppression mask over the sorted prefix ----------------
__global__ void mask_kernel() {
    int tid = blockIdx.x * blockDim.x + threadIdx.x;   // M1*W1 threads
    int i = tid / W1;
    int w = tid % W1;
    int jbase = w * 64;
    int n1 = g_ncand < M1 ? g_ncand : M1;

    unsigned long long bits = 0ULL;
    if (i < n1 && jbase + 63 > i) {
        float4 bi = g_sbox[i];
        float ai = g_sarea[i];
        int jj0 = (i + 1 > jbase) ? (i + 1 - jbase) : 0;
        int jjend = (jbase + 64 <= n1) ? 64 : (n1 - jbase);
        #pragma unroll 4
        for (int jj = jj0; jj < jjend; jj++) {
            int j = jbase + jj;
            if (iou_gt(bi, ai, g_sbox[j], g_sarea[j])) bits |= (1ULL << jj);
        }
    }
    g_mask[(size_t)i * W1 + w] = bits;
}

// ---------------- single-warp greedy bit-scan (+ serial continuation) ----------------
__global__ void scan_kernel() {
    int lane = threadIdx.x;            // 32 lanes; lane owns mask word `lane` of each row
    unsigned long long rem = 0ULL;     // accumulated suppression bits for lane's 64 js
    unsigned long long b[8];
    int ncand = g_ncand;
    int n1 = ncand < M1 ? ncand : M1;

    #pragma unroll
    for (int q = 0; q < 8; q++)
        b[q] = g_mask[(size_t)q * W1 + lane];

    int kept = 0;
    for (int p = 0; p < n1; p++) {
        int slot = p & 7;
        unsigned long long r = b[slot];
        int pf = p + 8;
        if (pf < M1) b[slot] = g_mask[(size_t)pf * W1 + lane];
        unsigned long long bw = __shfl_sync(0xffffffffu, rem, p >> 6);
        if (!((bw >> (p & 63)) & 1ULL)) {
            if (lane == 0) g_kept_idx[kept] = g_sorder[p];
            rem |= r;
            kept++;
            if (kept == MAXK) break;
        }
    }

    // continuation over remaining sorted candidates (rarely needed)
    if (kept < MAXK) {
        for (int p = M1; p < ncand && kept < MAXK; p++) {
            int orig = g_sorder[p];
            float4 bj = g_boxes[orig];
            float aj = g_area[orig];
            bool hit = false;
            for (int t = lane; t < kept; t += 32) {
                int k = g_kept_idx[t];
                if (iou_gt(g_boxes[k], g_area[k], bj, aj)) hit = true;
            }
            if (__ballot_sync(0xffffffffu, hit) == 0u) {
                if (lane == 0) g_kept_idx[kept] = orig;
                kept++;
            }
        }
    }

    if (lane == 0) {
        g_state[0] = kept;
        // Done only if we provably have the full keep list: 750 keeps found from a
        // complete, correctly-ordered candidate set.
        g_state[1] = (kept >= MAXK && !g_overflow) ? 1 : 0;
    }
}

// ---------------- full reference-style fallback (expected to no-op) ----------------
__global__ void __launch_bounds__(1024, 1) fallback_kernel(const float* __restrict__ scores) {
    if (g_state[1]) return;     // uniform read -> whole block exits immediately

    __shared__ float  rs[1024];
    __shared__ int    ri[1024];
    int tid = threadIdx.x;

    for (int w = tid; w < NSUPW; w += 1024) g_supp[w] = 0u;
    __syncthreads();

    int kept = 0;
    for (int it = 0; it < MAXK; it++) {
        // argmax over unsuppressed: max score, ties -> min index (stable argsort order)
        float bs = -1.0f; int bi = 0x7FFFFFFF;
        for (int i = tid; i < N_PRIORS; i += 1024) {
            if (!((g_supp[i >> 5] >> (i & 31)) & 1u)) {
                float s = scores[i];
                if (s > bs || (s == bs && i < bi)) { bs = s; bi = i; }
            }
        }
        rs[tid] = bs; ri[tid] = bi;
        __syncthreads();
        for (int off = 512; off > 0; off >>= 1) {
            if (tid < off) {
                float so = rs[tid + off]; int io = ri[tid + off];
                if (so > rs[tid] || (so == rs[tid] && io < ri[tid])) { rs[tid] = so; ri[tid] = io; }
            }
            __syncthreads();
        }
        float topS = rs[0]; int top = ri[0];
        __syncthreads();
        if (topS < 0.0f) break;     // all suppressed -> remaining keeps invalid (zero-filled)

        if (tid == 0) g_kept_idx[kept] = top;
        kept++;

        float4 bt = g_boxes[top];
        float at = g_area[top];
        for (int i = tid; i < N_PRIORS; i += 1024) {
            if (iou_gt(bt, at, g_boxes[i], g_area[i]))
                atomicOr(&g_supp[i >> 5], 1u << (i & 31));
        }
        __syncthreads();
    }
    if (tid == 0) { g_state[0] = kept; g_state[1] = 1; }
}

// ---------------- finalize: threshold + gather boxes/scores/landmarks ----------------
__global__ void finalize_kernel(const float* __restrict__ scores,
                                const float* __restrict__ landms,
                                const float* __restrict__ thrp,
                                float* __restrict__ out) {
    int i = blockIdx.x * blockDim.x + threadIdx.x;
    if (i >= MAXK) return;
    int kept = g_state[0];
    float thr = thrp[0];

    float* ob = out;                 // [750,4]
    float* os = out + MAXK * 4;      // [750]
    float* ol = out + MAXK * 5;      // [750,10]

    float4 b = make_float4(0.f, 0.f, 0.f, 0.f);
    float s = 0.f;
    float lm[10];
    #pragma unroll
    for (int j = 0; j < 10; j++) lm[j] = 0.f;

    if (i < kept) {
        int k = g_kept_idx[i];
        float sc = scores[k];
        if (sc > thr) {
            b = g_boxes[k];
            s = sc;
            float px, py, ps;
            get_prior(k, px, py, ps);
            #pragma unroll
            for (int j = 0; j < 5; j++) {
                float ox = landms[10 * k + 2 * j + 0];
                float oy = landms[10 * k + 2 * j + 1];
                lm[2 * j + 0] = __fmul_rn(__fadd_rn(px, __fmul_rn(__fmul_rn(ox, 0.1f), ps)), 2560.0f);
                lm[2 * j + 1] = __fmul_rn(__fadd_rn(py, __fmul_rn(__fmul_rn(oy, 0.1f), ps)), 2560.0f);
            }
        }
    }
    ob[4 * i + 0] = b.x;
    ob[4 * i + 1] = b.y;
    ob[4 * i + 2] = b.z;
    ob[4 * i + 3] = b.w;
    os[i] = s;
    #pragma unroll
    for (int j = 0; j < 10; j++) ol[10 * i + j] = lm[j];
}

// ---------------- launch ----------------
extern "C" void kernel_launch(void* const* d_in, const int* in_sizes, int n_in,
                              void* d_out, int out_size) {
    const float* bboxes = (const float*)d_in[0];   // (1, N, 4)
    const float* scores = (const float*)d_in[1];   // (1, N)
    const float* landms = (const float*)d_in[2];   // (1, N, 10)
    const float* thr    = (const float*)d_in[3];   // (1,)
    float* out = (float*)d_out;
    cudaStream_t stream = 0;

    init_kernel<<<1, 32, 0, stream>>>();
    decode_kernel<<<N_PRIORS / 256, 256, 0, stream>>>(bboxes, scores);
    sort_kernel<<<1, 1024, 0, stream>>>();
    mask_kernel<<<(M1 * W1) / 256, 256, 0, stream>>>();
    scan_kernel<<<1, 32, 0, stream>>>();
    fallback_kernel<<<1, 1024, 0, stream>>>(scores);
    finalize_kernel<<<(MAXK + 255) / 256, 256, 0, stream>>>(scores, landms, thr, out);
}